// round 14
// baseline (speedup 1.0000x reference)
#include <cuda_runtime.h>
#include <cuda_fp16.h>
#include <math.h>

#define OBS 17
#define ACT 4
#define HID 64
#define LOG_2PI 1.8378770664093453f
#define TPB 64
typedef unsigned long long ull;

// ---- shared buffer layout (float offsets), one union for both branches ----
#define F_W1   0       // 17*64 = 1088
#define F_W2   1088    // 64*64 = 4096
#define F_W3   5184    // actor: 64*4 = 256 ; critic: 64
#define F_B1   5440    // 64
#define F_B2   5504    // 64
#define F_B3   5568    // 4 (actor bias3)
#define F_LOG  5572    // 4
#define F_INV  5576    // 4
#define F_QINV 5584    // 16
#define F_MISC 5600    // 0: s0|cb3, 1: entropy
#define SM_FLOATS 5604

__device__ __forceinline__ float tanh_fast(float v) {
    float r; asm("tanh.approx.f32 %0, %1;" : "=f"(r) : "f"(v)); return r;
}
__device__ __forceinline__ ull fma2(ull a, ull b, ull c) {
    ull d; asm("fma.rn.f32x2 %0, %1, %2, %3;" : "=l"(d) : "l"(a), "l"(b), "l"(c)); return d;
}
__device__ __forceinline__ ull dup2(float v) {
    ull d; asm("mov.b64 %0, {%1, %1};" : "=l"(d) : "f"(v)); return d;
}
__device__ __forceinline__ ull pk2(float x, float y) {
    ull d; asm("mov.b64 %0, {%1, %2};" : "=l"(d) : "f"(x), "f"(y)); return d;
}
__device__ __forceinline__ float2 upk(ull p) {
    float2 r; asm("mov.b64 {%0, %1}, %2;" : "=f"(r.x), "=f"(r.y) : "l"(p)); return r;
}

// fp32 4x4 SPD inverse: Gauss-Jordan w/ pivoting + 2 Newton refinements.
__device__ void qinv_f32(const float* __restrict__ L, float* __restrict__ outQinv) {
    float Q[16], M[4][8];
#pragma unroll
    for (int i = 0; i < 4; i++)
#pragma unroll
        for (int j = 0; j < 4; j++) {
            float s = (i == j) ? 1e-4f : 0.0f;
#pragma unroll
            for (int k = 0; k < 4; k++)
                if (k <= i && k <= j) s += L[i * 4 + k] * L[j * 4 + k];
            Q[i * 4 + j] = s;
        }
#pragma unroll
    for (int i = 0; i < 4; i++)
#pragma unroll
        for (int j = 0; j < 4; j++) {
            M[i][j] = Q[i * 4 + j];
            M[i][4 + j] = (i == j) ? 1.0f : 0.0f;
        }
    for (int c = 0; c < 4; c++) {
        int p = c;
        for (int r = c + 1; r < 4; r++) if (fabsf(M[r][c]) > fabsf(M[p][c])) p = r;
        if (p != c)
            for (int j = 0; j < 8; j++) { float t = M[c][j]; M[c][j] = M[p][j]; M[p][j] = t; }
        const float inv = 1.0f / M[c][c];
        for (int j = 0; j < 8; j++) M[c][j] *= inv;
        for (int r = 0; r < 4; r++) if (r != c) {
            const float f = M[r][c];
            for (int j = 0; j < 8; j++) M[r][j] -= f * M[c][j];
        }
    }
    float X[16];
#pragma unroll
    for (int i = 0; i < 4; i++)
#pragma unroll
        for (int j = 0; j < 4; j++) X[i * 4 + j] = M[i][4 + j];
#pragma unroll 1
    for (int it = 0; it < 2; it++) {
        float R[16];
#pragma unroll
        for (int i = 0; i < 4; i++)
#pragma unroll
            for (int j = 0; j < 4; j++) {
                float s = (i == j) ? 2.0f : 0.0f;
#pragma unroll
                for (int k = 0; k < 4; k++) s -= Q[i * 4 + k] * X[k * 4 + j];
                R[i * 4 + j] = s;
            }
        float Xn[16];
#pragma unroll
        for (int i = 0; i < 4; i++)
#pragma unroll
            for (int j = 0; j < 4; j++) {
                float s = 0.0f;
#pragma unroll
                for (int k = 0; k < 4; k++) s += X[i * 4 + k] * R[k * 4 + j];
                Xn[i * 4 + j] = s;
            }
#pragma unroll
        for (int i = 0; i < 16; i++) X[i] = Xn[i];
    }
#pragma unroll
    for (int i = 0; i < 16; i++) outQinv[i] = X[i];
}

// ---------------------------------------------------------------------------
// Fat-grid kernel, TPB=64 for fine residency granularity.
// blocks [0, half) = actor, [half, 2*half) = critic; 2 rows/thread.
// ---------------------------------------------------------------------------
__global__ __launch_bounds__(TPB, 6) void fused_kernel(
    const float* __restrict__ x, const float* __restrict__ sdfs,
    const float* __restrict__ grads, const float* __restrict__ f_x,
    const float* __restrict__ g_x, const float* __restrict__ action,
    const float* __restrict__ cW1, const float* __restrict__ cb1,
    const float* __restrict__ cW2, const float* __restrict__ cb2,
    const float* __restrict__ cW3, const float* __restrict__ cb3,
    const float* __restrict__ aW1, const float* __restrict__ ab1,
    const float* __restrict__ aW2, const float* __restrict__ ab2,
    const float* __restrict__ aW3, const float* __restrict__ ab3,
    const float* __restrict__ logstd, const float* __restrict__ L,
    const float* __restrict__ s0,
    float* __restrict__ out, int N, int halfBlocks)
{
    __shared__ __align__(16) float sm[SM_FLOATS];
    const int tid = threadIdx.x;
    const bool isActor = (int)blockIdx.x < halfBlocks;
    const int blk = isActor ? (int)blockIdx.x : (int)blockIdx.x - halfBlocks;

    // ================= staging =================
    if (isActor) {
        for (int i = tid; i < OBS * HID; i += TPB) sm[F_W1 + i] = aW1[i];
        for (int i = tid; i < HID * HID; i += TPB) sm[F_W2 + i] = aW2[i];
        for (int i = tid; i < HID * ACT; i += TPB) sm[F_W3 + i] = aW3[i];
        if (tid < HID) { sm[F_B1 + tid] = ab1[tid]; sm[F_B2 + tid] = ab2[tid]; }
        if (tid >= 4 && tid < 8) {
            const int a = tid - 4;
            const float ls = logstd[a];
            sm[F_B3 + a] = ab3[a]; sm[F_LOG + a] = ls; sm[F_INV + a] = expf(-ls);
        }
        if (tid == 1) {
            sm[F_MISC + 0] = s0[0];
            float e = 0.0f;
            for (int a = 0; a < ACT; a++) e += 0.5f + 0.5f * LOG_2PI + logstd[a];
            sm[F_MISC + 1] = e;
        }
        if (tid == 0) qinv_f32(L, &sm[F_QINV]);
    } else {
        for (int i = tid; i < OBS * HID; i += TPB) sm[F_W1 + i] = cW1[i];
        for (int i = tid; i < HID * HID; i += TPB) sm[F_W2 + i] = cW2[i];
        if (tid < HID) {
            sm[F_W3 + tid] = cW3[tid];
            sm[F_B1 + tid] = cb1[tid];
            sm[F_B2 + tid] = cb2[tid];
        }
        if (tid == 0) sm[F_MISC + 0] = cb3[0];
    }
    __syncthreads();

    const int r0 = blk * (2 * TPB) + tid;
    const int r1 = r0 + TPB;
    const bool ok0 = r0 < N, ok1 = r1 < N;
    const int rl0 = ok0 ? r0 : 0;
    const int rl1 = ok1 ? r1 : 0;

    __half2 h1A[32], h1B[32];

    // ================= layer 1 =================
    {
        float xA[OBS], xB[OBS];
#pragma unroll
        for (int i = 0; i < OBS; i++) { xA[i] = x[rl0 * OBS + i]; xB[i] = x[rl1 * OBS + i]; }
#pragma unroll 1
        for (int c1 = 0; c1 < 2; c1++) {
            ull hA[16], hB[16];
            const ulonglong2* bp = (const ulonglong2*)&sm[F_B1 + c1 * 32];
#pragma unroll
            for (int q = 0; q < 8; q++) {
                ulonglong2 bb = bp[q];
                hA[2*q] = bb.x; hA[2*q+1] = bb.y;
                hB[2*q] = bb.x; hB[2*q+1] = bb.y;
            }
#pragma unroll 1
            for (int i = 0; i < OBS; i++) {
                const ull vA = dup2(xA[i]), vB = dup2(xB[i]);
                const ulonglong2* wp = (const ulonglong2*)&sm[F_W1 + i * HID + c1 * 32];
#pragma unroll
                for (int q = 0; q < 8; q++) {
                    ulonglong2 ww = wp[q];
                    hA[2*q]   = fma2(ww.x, vA, hA[2*q]);
                    hA[2*q+1] = fma2(ww.y, vA, hA[2*q+1]);
                    hB[2*q]   = fma2(ww.x, vB, hB[2*q]);
                    hB[2*q+1] = fma2(ww.y, vB, hB[2*q+1]);
                }
            }
#pragma unroll
            for (int p = 0; p < 16; p++) {
                float2 t = upk(hA[p]);
                h1A[c1 * 16 + p] = __floats2half2_rn(tanh_fast(t.x), tanh_fast(t.y));
                t = upk(hB[p]);
                h1B[c1 * 16 + p] = __floats2half2_rn(tanh_fast(t.x), tanh_fast(t.y));
            }
        }
    }

    // ================= layer 2 + fused layer 3 =================
    ull mA01, mA23, mB01, mB23;   // actor: mean pairs ; critic: value in mA01/mB01
    if (isActor) {
        mA01 = pk2(sm[F_B3 + 0], sm[F_B3 + 1]);
        mA23 = pk2(sm[F_B3 + 2], sm[F_B3 + 3]);
        mB01 = mA01; mB23 = mA23;
    } else {
        mA01 = pk2(sm[F_MISC + 0], 0.0f);
        mB01 = mA01; mA23 = 0ull; mB23 = 0ull;
    }
#pragma unroll 1
    for (int c = 0; c < 4; c++) {
        ull aA[8], aB[8];
        const ulonglong2* bp = (const ulonglong2*)&sm[F_B2 + c * 16];
#pragma unroll
        for (int q = 0; q < 4; q++) {
            ulonglong2 bb = bp[q];
            aA[2*q] = bb.x; aA[2*q+1] = bb.y;
            aB[2*q] = bb.x; aB[2*q+1] = bb.y;
        }
#pragma unroll 4
        for (int ii = 0; ii < 32; ii++) {
            const float2 fA = __half22float2(h1A[ii]);
            const float2 fB = __half22float2(h1B[ii]);
            const ull a0 = dup2(fA.x), a1 = dup2(fA.y);
            const ull b0 = dup2(fB.x), b1 = dup2(fB.y);
            const ulonglong2* wp0 = (const ulonglong2*)&sm[F_W2 + (2*ii) * HID + c * 16];
            const ulonglong2* wp1 = (const ulonglong2*)&sm[F_W2 + (2*ii + 1) * HID + c * 16];
#pragma unroll
            for (int q = 0; q < 4; q++) {
                ulonglong2 w0 = wp0[q];
                aA[2*q]   = fma2(w0.x, a0, aA[2*q]);
                aA[2*q+1] = fma2(w0.y, a0, aA[2*q+1]);
                aB[2*q]   = fma2(w0.x, b0, aB[2*q]);
                aB[2*q+1] = fma2(w0.y, b0, aB[2*q+1]);
            }
#pragma unroll
            for (int q = 0; q < 4; q++) {
                ulonglong2 w1 = wp1[q];
                aA[2*q]   = fma2(w1.x, a1, aA[2*q]);
                aA[2*q+1] = fma2(w1.y, a1, aA[2*q+1]);
                aB[2*q]   = fma2(w1.x, b1, aB[2*q]);
                aB[2*q+1] = fma2(w1.y, b1, aB[2*q+1]);
            }
        }
#pragma unroll
        for (int p = 0; p < 8; p++) {
            const int j = c * 16 + 2 * p;
            float2 tA = upk(aA[p]);
            tA.x = tanh_fast(tA.x); tA.y = tanh_fast(tA.y);
            float2 tB = upk(aB[p]);
            tB.x = tanh_fast(tB.x); tB.y = tanh_fast(tB.y);
            if (isActor) {
                const ulonglong2 w0 = *(const ulonglong2*)&sm[F_W3 + j * ACT];
                const ulonglong2 w1 = *(const ulonglong2*)&sm[F_W3 + (j + 1) * ACT];
                ull d;
                d = dup2(tA.x); mA01 = fma2(w0.x, d, mA01); mA23 = fma2(w0.y, d, mA23);
                d = dup2(tA.y); mA01 = fma2(w1.x, d, mA01); mA23 = fma2(w1.y, d, mA23);
                d = dup2(tB.x); mB01 = fma2(w0.x, d, mB01); mB23 = fma2(w0.y, d, mB23);
                d = dup2(tB.y); mB01 = fma2(w1.x, d, mB01); mB23 = fma2(w1.y, d, mB23);
            } else {
                const ull wv = *(const ull*)&sm[F_W3 + j];
                mA01 = fma2(wv, pk2(tA.x, tA.y), mA01);
                mB01 = fma2(wv, pk2(tB.x, tB.y), mB01);
            }
        }
    }

    // ================= outputs =================
    if (!isActor) {
        const float2 a = upk(mA01);
        const float2 b = upk(mB01);
        if (ok0) out[6 * N + r0] = a.x + a.y;
        if (ok1) out[6 * N + r1] = b.x + b.y;
        return;
    }

#pragma unroll 1
    for (int rr = 0; rr < 2; rr++) {
        const int row = rr ? r1 : r0;
        const bool ok = rr ? ok1 : ok0;
        const int rl = ok ? row : 0;
        float m0, m1, m2, m3;
        {
            const float2 a = upk(rr ? mB01 : mA01);
            const float2 b = upk(rr ? mB23 : mA23);
            m0 = a.x; m1 = a.y; m2 = b.x; m3 = b.y;
        }
        float G0 = 0.f, G1 = 0.f, G2 = 0.f, G3 = 0.f, gf = 0.f;
#pragma unroll
        for (int s = 0; s < OBS; s++) {
            const float gr = grads[rl * OBS + s];
            const float4 gx = *(const float4*)&g_x[rl * OBS * ACT + s * ACT];
            G0 -= gr * gx.x; G1 -= gr * gx.y; G2 -= gr * gx.z; G3 -= gr * gx.w;
            gf += gr * f_x[rl * OBS + s];
        }
        const float4 av = *(const float4*)&action[rl * ACT];
        const float h = sm[F_MISC + 0] + sdfs[rl] + gf
                      - (G0 * av.x + G1 * av.y + G2 * av.z + G3 * av.w);
        const float* q = &sm[F_QINV];
        const float v0 = q[0]  * G0 + q[1]  * G1 + q[2]  * G2 + q[3]  * G3;
        const float v1 = q[4]  * G0 + q[5]  * G1 + q[6]  * G2 + q[7]  * G3;
        const float v2 = q[8]  * G0 + q[9]  * G1 + q[10] * G2 + q[11] * G3;
        const float v3 = q[12] * G0 + q[13] * G1 + q[14] * G2 + q[15] * G3;
        const float denom = G0 * v0 + G1 * v1 + G2 * v2 + G3 * v3;
        const float lam = fmaxf(0.0f, -h / denom);
        const float z0 = (av.x - m0) * sm[F_INV + 0];
        const float z1 = (av.y - m1) * sm[F_INV + 1];
        const float z2 = (av.z - m2) * sm[F_INV + 2];
        const float z3 = (av.w - m3) * sm[F_INV + 3];
        const float lp = -0.5f * (z0*z0 + z1*z1 + z2*z2 + z3*z3)
                       - (sm[F_LOG + 0] + sm[F_LOG + 1] + sm[F_LOG + 2] + sm[F_LOG + 3])
                       - 2.0f * LOG_2PI;
        if (ok) {
            *(float4*)&out[row * 4] = make_float4(m0 - lam * v0, m1 - lam * v1,
                                                  m2 - lam * v2, m3 - lam * v3);
            out[4 * N + row] = lp;
            out[5 * N + row] = sm[F_MISC + 1];
        }
    }
}

extern "C" void kernel_launch(void* const* d_in, const int* in_sizes, int n_in,
                              void* d_out, int out_size) {
    const float* x      = (const float*)d_in[0];
    const float* sdfs   = (const float*)d_in[1];
    const float* grads  = (const float*)d_in[2];
    const float* f_x    = (const float*)d_in[3];
    const float* g_x    = (const float*)d_in[4];
    const float* action = (const float*)d_in[5];
    const float* cW1 = (const float*)d_in[6];
    const float* cb1 = (const float*)d_in[7];
    const float* cW2 = (const float*)d_in[8];
    const float* cb2 = (const float*)d_in[9];
    const float* cW3 = (const float*)d_in[10];
    const float* cb3 = (const float*)d_in[11];
    const float* aW1 = (const float*)d_in[12];
    const float* ab1 = (const float*)d_in[13];
    const float* aW2 = (const float*)d_in[14];
    const float* ab2 = (const float*)d_in[15];
    const float* aW3 = (const float*)d_in[16];
    const float* ab3 = (const float*)d_in[17];
    const float* logstd = (const float*)d_in[18];
    const float* L      = (const float*)d_in[19];
    const float* s0     = (const float*)d_in[20];

    const int N = in_sizes[0] / OBS;
    float* out = (float*)d_out;

    // Large shared carveout so ~6 x 22.4KB blocks can be resident.
    cudaFuncSetAttribute(fused_kernel,
                         cudaFuncAttributePreferredSharedMemoryCarveout, 100);

    const int rowsPerBlock = 2 * TPB;
    const int halfBlocks = (N + rowsPerBlock - 1) / rowsPerBlock;
    fused_kernel<<<2 * halfBlocks, TPB>>>(x, sdfs, grads, f_x, g_x, action,
                                          cW1, cb1, cW2, cb2, cW3, cb3,
                                          aW1, ab1, aW2, ab2, aW3, ab3,
                                          logstd, L, s0, out, N, halfBlocks);
}

// round 15
// speedup vs baseline: 1.1469x; 1.1469x over previous
#include <cuda_runtime.h>
#include <cuda_fp16.h>
#include <math.h>

#define OBS 17
#define ACT 4
#define HID 64
#define LOG_2PI 1.8378770664093453f
#define TPB 128
typedef unsigned long long ull;

// ---- shared buffer layout (float offsets) ----
#define F_W1   0       // 17*64 = 1088
#define F_W2   1088    // 64*64 = 4096
#define F_W3   5184    // actor: 256 ; critic: 64
#define F_B1   5440    // 64
#define F_B2   5504    // 64
#define F_B3   5568    // 4
#define F_LOG  5572    // 4
#define F_INV  5576    // 4
#define F_QINV 5584    // 16
#define F_MISC 5600    // 0: s0|cb3, 1: entropy
#define F_XG   5604    // 256*17 = 4352 : x tile, later reused for grads tile
#define F_FX   9956    // 256*17 = 4352 : f_x tile (actor only)
#define SM_FLOATS 14308

__device__ __forceinline__ float tanh_fast(float v) {
    float r; asm("tanh.approx.f32 %0, %1;" : "=f"(r) : "f"(v)); return r;
}
__device__ __forceinline__ ull fma2(ull a, ull b, ull c) {
    ull d; asm("fma.rn.f32x2 %0, %1, %2, %3;" : "=l"(d) : "l"(a), "l"(b), "l"(c)); return d;
}
__device__ __forceinline__ ull dup2(float v) {
    ull d; asm("mov.b64 %0, {%1, %1};" : "=l"(d) : "f"(v)); return d;
}
__device__ __forceinline__ ull pk2(float x, float y) {
    ull d; asm("mov.b64 %0, {%1, %2};" : "=l"(d) : "f"(x), "f"(y)); return d;
}
__device__ __forceinline__ float2 upk(ull p) {
    float2 r; asm("mov.b64 {%0, %1}, %2;" : "=f"(r.x), "=f"(r.y) : "l"(p)); return r;
}

// fp32 4x4 SPD inverse: Gauss-Jordan w/ pivoting + 2 Newton refinements.
__device__ void qinv_f32(const float* __restrict__ L, float* __restrict__ outQinv) {
    float Q[16], M[4][8];
#pragma unroll
    for (int i = 0; i < 4; i++)
#pragma unroll
        for (int j = 0; j < 4; j++) {
            float s = (i == j) ? 1e-4f : 0.0f;
#pragma unroll
            for (int k = 0; k < 4; k++)
                if (k <= i && k <= j) s += L[i * 4 + k] * L[j * 4 + k];
            Q[i * 4 + j] = s;
        }
#pragma unroll
    for (int i = 0; i < 4; i++)
#pragma unroll
        for (int j = 0; j < 4; j++) {
            M[i][j] = Q[i * 4 + j];
            M[i][4 + j] = (i == j) ? 1.0f : 0.0f;
        }
    for (int c = 0; c < 4; c++) {
        int p = c;
        for (int r = c + 1; r < 4; r++) if (fabsf(M[r][c]) > fabsf(M[p][c])) p = r;
        if (p != c)
            for (int j = 0; j < 8; j++) { float t = M[c][j]; M[c][j] = M[p][j]; M[p][j] = t; }
        const float inv = 1.0f / M[c][c];
        for (int j = 0; j < 8; j++) M[c][j] *= inv;
        for (int r = 0; r < 4; r++) if (r != c) {
            const float f = M[r][c];
            for (int j = 0; j < 8; j++) M[r][j] -= f * M[c][j];
        }
    }
    float X[16];
#pragma unroll
    for (int i = 0; i < 4; i++)
#pragma unroll
        for (int j = 0; j < 4; j++) X[i * 4 + j] = M[i][4 + j];
#pragma unroll 1
    for (int it = 0; it < 2; it++) {
        float R[16];
#pragma unroll
        for (int i = 0; i < 4; i++)
#pragma unroll
            for (int j = 0; j < 4; j++) {
                float s = (i == j) ? 2.0f : 0.0f;
#pragma unroll
                for (int k = 0; k < 4; k++) s -= Q[i * 4 + k] * X[k * 4 + j];
                R[i * 4 + j] = s;
            }
        float Xn[16];
#pragma unroll
        for (int i = 0; i < 4; i++)
#pragma unroll
            for (int j = 0; j < 4; j++) {
                float s = 0.0f;
#pragma unroll
                for (int k = 0; k < 4; k++) s += X[i * 4 + k] * R[k * 4 + j];
                Xn[i * 4 + j] = s;
            }
#pragma unroll
        for (int i = 0; i < 16; i++) X[i] = Xn[i];
    }
#pragma unroll
    for (int i = 0; i < 16; i++) outQinv[i] = X[i];
}

// ---------------------------------------------------------------------------
// Fat-grid kernel with coalesced smem staging for strided row arrays.
// blocks [0, half) = actor, [half, 2*half) = critic; 2 rows/thread.
// ---------------------------------------------------------------------------
__global__ __launch_bounds__(TPB, 3) void fused_kernel(
    const float* __restrict__ x, const float* __restrict__ sdfs,
    const float* __restrict__ grads, const float* __restrict__ f_x,
    const float* __restrict__ g_x, const float* __restrict__ action,
    const float* __restrict__ cW1, const float* __restrict__ cb1,
    const float* __restrict__ cW2, const float* __restrict__ cb2,
    const float* __restrict__ cW3, const float* __restrict__ cb3,
    const float* __restrict__ aW1, const float* __restrict__ ab1,
    const float* __restrict__ aW2, const float* __restrict__ ab2,
    const float* __restrict__ aW3, const float* __restrict__ ab3,
    const float* __restrict__ logstd, const float* __restrict__ L,
    const float* __restrict__ s0,
    float* __restrict__ out, int N, int halfBlocks)
{
    __shared__ __align__(16) float sm[SM_FLOATS];
    const int tid = threadIdx.x;
    const bool isActor = (int)blockIdx.x < halfBlocks;
    const int blk = isActor ? (int)blockIdx.x : (int)blockIdx.x - halfBlocks;
    const int rowsPB = 2 * TPB;
    const int blockStart = blk * rowsPB;
    const bool fullBlk = (blockStart + rowsPB) <= N;

    // ================= staging =================
    if (isActor) {
        for (int i = tid; i < OBS * HID; i += TPB) sm[F_W1 + i] = aW1[i];
        for (int i = tid; i < HID * HID; i += TPB) sm[F_W2 + i] = aW2[i];
        for (int i = tid; i < HID * ACT; i += TPB) sm[F_W3 + i] = aW3[i];
        if (tid < HID) { sm[F_B1 + tid] = ab1[tid]; sm[F_B2 + tid] = ab2[tid]; }
        if (tid >= 64 && tid < 68) {
            const int a = tid - 64;
            const float ls = logstd[a];
            sm[F_B3 + a] = ab3[a]; sm[F_LOG + a] = ls; sm[F_INV + a] = expf(-ls);
        }
        if (tid == 1) {
            sm[F_MISC + 0] = s0[0];
            float e = 0.0f;
            for (int a = 0; a < ACT; a++) e += 0.5f + 0.5f * LOG_2PI + logstd[a];
            sm[F_MISC + 1] = e;
        }
        if (tid == 0) qinv_f32(L, &sm[F_QINV]);
    } else {
        for (int i = tid; i < OBS * HID; i += TPB) sm[F_W1 + i] = cW1[i];
        for (int i = tid; i < HID * HID; i += TPB) sm[F_W2 + i] = cW2[i];
        if (tid < HID) {
            sm[F_W3 + tid] = cW3[tid];
            sm[F_B1 + tid] = cb1[tid];
            sm[F_B2 + tid] = cb2[tid];
        }
        if (tid == 0) sm[F_MISC + 0] = cb3[0];
    }

    // ---- stage x tile (coalesced), + f_x tile for actor ----
    if (fullBlk) {
        const float4* gx4 = (const float4*)(x + blockStart * OBS);
        float4* sx4 = (float4*)&sm[F_XG];
        for (int i = tid; i < rowsPB * OBS / 4; i += TPB) sx4[i] = gx4[i];
        if (isActor) {
            const float4* gf4 = (const float4*)(f_x + blockStart * OBS);
            float4* sf4 = (float4*)&sm[F_FX];
            for (int i = tid; i < rowsPB * OBS / 4; i += TPB) sf4[i] = gf4[i];
        }
    } else {
        const int lim = N * OBS;
        for (int i = tid; i < rowsPB * OBS; i += TPB) {
            const int g = blockStart * OBS + i;
            sm[F_XG + i] = (g < lim) ? x[g] : 0.0f;
        }
        if (isActor)
            for (int i = tid; i < rowsPB * OBS; i += TPB) {
                const int g = blockStart * OBS + i;
                sm[F_FX + i] = (g < lim) ? f_x[g] : 0.0f;
            }
    }
    __syncthreads();

    const int r0 = blockStart + tid;
    const int r1 = r0 + TPB;
    const bool ok0 = r0 < N, ok1 = r1 < N;

    __half2 h1A[32], h1B[32];

    // ================= layer 1 (x read from smem, conflict-free) =================
#pragma unroll 1
    for (int c1 = 0; c1 < 2; c1++) {
        ull hA[16], hB[16];
        const ulonglong2* bp = (const ulonglong2*)&sm[F_B1 + c1 * 32];
#pragma unroll
        for (int q = 0; q < 8; q++) {
            ulonglong2 bb = bp[q];
            hA[2*q] = bb.x; hA[2*q+1] = bb.y;
            hB[2*q] = bb.x; hB[2*q+1] = bb.y;
        }
#pragma unroll 1
        for (int i = 0; i < OBS; i++) {
            const ull vA = dup2(sm[F_XG + tid * OBS + i]);
            const ull vB = dup2(sm[F_XG + (tid + TPB) * OBS + i]);
            const ulonglong2* wp = (const ulonglong2*)&sm[F_W1 + i * HID + c1 * 32];
#pragma unroll
            for (int q = 0; q < 8; q++) {
                ulonglong2 ww = wp[q];
                hA[2*q]   = fma2(ww.x, vA, hA[2*q]);
                hA[2*q+1] = fma2(ww.y, vA, hA[2*q+1]);
                hB[2*q]   = fma2(ww.x, vB, hB[2*q]);
                hB[2*q+1] = fma2(ww.y, vB, hB[2*q+1]);
            }
        }
#pragma unroll
        for (int p = 0; p < 16; p++) {
            float2 t = upk(hA[p]);
            h1A[c1 * 16 + p] = __floats2half2_rn(tanh_fast(t.x), tanh_fast(t.y));
            t = upk(hB[p]);
            h1B[c1 * 16 + p] = __floats2half2_rn(tanh_fast(t.x), tanh_fast(t.y));
        }
    }

    // ---- x tile dead: reuse F_XG for grads tile (actor only) ----
    __syncthreads();
    if (isActor) {
        if (fullBlk) {
            const float4* gg4 = (const float4*)(grads + blockStart * OBS);
            float4* sg4 = (float4*)&sm[F_XG];
            for (int i = tid; i < rowsPB * OBS / 4; i += TPB) sg4[i] = gg4[i];
        } else {
            const int lim = N * OBS;
            for (int i = tid; i < rowsPB * OBS; i += TPB) {
                const int g = blockStart * OBS + i;
                sm[F_XG + i] = (g < lim) ? grads[g] : 0.0f;
            }
        }
    }
    __syncthreads();

    // ================= layer 2 + fused layer 3 =================
    ull mA01, mA23, mB01, mB23;   // actor: mean pairs ; critic: value in mA01/mB01
    if (isActor) {
        mA01 = pk2(sm[F_B3 + 0], sm[F_B3 + 1]);
        mA23 = pk2(sm[F_B3 + 2], sm[F_B3 + 3]);
        mB01 = mA01; mB23 = mA23;
    } else {
        mA01 = pk2(sm[F_MISC + 0], 0.0f);
        mB01 = mA01; mA23 = 0ull; mB23 = 0ull;
    }
#pragma unroll 1
    for (int c = 0; c < 4; c++) {
        ull aA[8], aB[8];
        const ulonglong2* bp = (const ulonglong2*)&sm[F_B2 + c * 16];
#pragma unroll
        for (int q = 0; q < 4; q++) {
            ulonglong2 bb = bp[q];
            aA[2*q] = bb.x; aA[2*q+1] = bb.y;
            aB[2*q] = bb.x; aB[2*q+1] = bb.y;
        }
#pragma unroll 4
        for (int ii = 0; ii < 32; ii++) {
            const float2 fA = __half22float2(h1A[ii]);
            const float2 fB = __half22float2(h1B[ii]);
            const ull a0 = dup2(fA.x), a1 = dup2(fA.y);
            const ull b0 = dup2(fB.x), b1 = dup2(fB.y);
            const ulonglong2* wp0 = (const ulonglong2*)&sm[F_W2 + (2*ii) * HID + c * 16];
            const ulonglong2* wp1 = (const ulonglong2*)&sm[F_W2 + (2*ii + 1) * HID + c * 16];
#pragma unroll
            for (int q = 0; q < 4; q++) {
                ulonglong2 w0 = wp0[q];
                aA[2*q]   = fma2(w0.x, a0, aA[2*q]);
                aA[2*q+1] = fma2(w0.y, a0, aA[2*q+1]);
                aB[2*q]   = fma2(w0.x, b0, aB[2*q]);
                aB[2*q+1] = fma2(w0.y, b0, aB[2*q+1]);
            }
#pragma unroll
            for (int q = 0; q < 4; q++) {
                ulonglong2 w1 = wp1[q];
                aA[2*q]   = fma2(w1.x, a1, aA[2*q]);
                aA[2*q+1] = fma2(w1.y, a1, aA[2*q+1]);
                aB[2*q]   = fma2(w1.x, b1, aB[2*q]);
                aB[2*q+1] = fma2(w1.y, b1, aB[2*q+1]);
            }
        }
#pragma unroll
        for (int p = 0; p < 8; p++) {
            const int j = c * 16 + 2 * p;
            float2 tA = upk(aA[p]);
            tA.x = tanh_fast(tA.x); tA.y = tanh_fast(tA.y);
            float2 tB = upk(aB[p]);
            tB.x = tanh_fast(tB.x); tB.y = tanh_fast(tB.y);
            if (isActor) {
                const ulonglong2 w0 = *(const ulonglong2*)&sm[F_W3 + j * ACT];
                const ulonglong2 w1 = *(const ulonglong2*)&sm[F_W3 + (j + 1) * ACT];
                ull d;
                d = dup2(tA.x); mA01 = fma2(w0.x, d, mA01); mA23 = fma2(w0.y, d, mA23);
                d = dup2(tA.y); mA01 = fma2(w1.x, d, mA01); mA23 = fma2(w1.y, d, mA23);
                d = dup2(tB.x); mB01 = fma2(w0.x, d, mB01); mB23 = fma2(w0.y, d, mB23);
                d = dup2(tB.y); mB01 = fma2(w1.x, d, mB01); mB23 = fma2(w1.y, d, mB23);
            } else {
                const ull wv = *(const ull*)&sm[F_W3 + j];
                mA01 = fma2(wv, pk2(tA.x, tA.y), mA01);
                mB01 = fma2(wv, pk2(tB.x, tB.y), mB01);
            }
        }
    }

    // ================= outputs =================
    if (!isActor) {
        const float2 a = upk(mA01);
        const float2 b = upk(mB01);
        if (ok0) out[6 * N + r0] = a.x + a.y;
        if (ok1) out[6 * N + r1] = b.x + b.y;
        return;
    }

#pragma unroll 1
    for (int rr = 0; rr < 2; rr++) {
        const int row = rr ? r1 : r0;
        const bool ok = rr ? ok1 : ok0;
        const int rl = ok ? row : 0;
        const int rowLocal = tid + rr * TPB;
        float m0, m1, m2, m3;
        {
            const float2 a = upk(rr ? mB01 : mA01);
            const float2 b = upk(rr ? mB23 : mA23);
            m0 = a.x; m1 = a.y; m2 = b.x; m3 = b.y;
        }
        float G0 = 0.f, G1 = 0.f, G2 = 0.f, G3 = 0.f, gf = 0.f;
#pragma unroll
        for (int s = 0; s < OBS; s++) {
            const float gr = sm[F_XG + rowLocal * OBS + s];   // grads (staged)
            const float4 gx = *(const float4*)&g_x[rl * OBS * ACT + s * ACT];
            G0 -= gr * gx.x; G1 -= gr * gx.y; G2 -= gr * gx.z; G3 -= gr * gx.w;
            gf += gr * sm[F_FX + rowLocal * OBS + s];          // f_x (staged)
        }
        const float4 av = *(const float4*)&action[rl * ACT];
        const float h = sm[F_MISC + 0] + sdfs[rl] + gf
                      - (G0 * av.x + G1 * av.y + G2 * av.z + G3 * av.w);
        const float* q = &sm[F_QINV];
        const float v0 = q[0]  * G0 + q[1]  * G1 + q[2]  * G2 + q[3]  * G3;
        const float v1 = q[4]  * G0 + q[5]  * G1 + q[6]  * G2 + q[7]  * G3;
        const float v2 = q[8]  * G0 + q[9]  * G1 + q[10] * G2 + q[11] * G3;
        const float v3 = q[12] * G0 + q[13] * G1 + q[14] * G2 + q[15] * G3;
        const float denom = G0 * v0 + G1 * v1 + G2 * v2 + G3 * v3;
        const float lam = fmaxf(0.0f, -h / denom);
        const float z0 = (av.x - m0) * sm[F_INV + 0];
        const float z1 = (av.y - m1) * sm[F_INV + 1];
        const float z2 = (av.z - m2) * sm[F_INV + 2];
        const float z3 = (av.w - m3) * sm[F_INV + 3];
        const float lp = -0.5f * (z0*z0 + z1*z1 + z2*z2 + z3*z3)
                       - (sm[F_LOG + 0] + sm[F_LOG + 1] + sm[F_LOG + 2] + sm[F_LOG + 3])
                       - 2.0f * LOG_2PI;
        if (ok) {
            *(float4*)&out[row * 4] = make_float4(m0 - lam * v0, m1 - lam * v1,
                                                  m2 - lam * v2, m3 - lam * v3);
            out[4 * N + row] = lp;
            out[5 * N + row] = sm[F_MISC + 1];
        }
    }
}

extern "C" void kernel_launch(void* const* d_in, const int* in_sizes, int n_in,
                              void* d_out, int out_size) {
    const float* x      = (const float*)d_in[0];
    const float* sdfs   = (const float*)d_in[1];
    const float* grads  = (const float*)d_in[2];
    const float* f_x    = (const float*)d_in[3];
    const float* g_x    = (const float*)d_in[4];
    const float* action = (const float*)d_in[5];
    const float* cW1 = (const float*)d_in[6];
    const float* cb1 = (const float*)d_in[7];
    const float* cW2 = (const float*)d_in[8];
    const float* cb2 = (const float*)d_in[9];
    const float* cW3 = (const float*)d_in[10];
    const float* cb3 = (const float*)d_in[11];
    const float* aW1 = (const float*)d_in[12];
    const float* ab1 = (const float*)d_in[13];
    const float* aW2 = (const float*)d_in[14];
    const float* ab2 = (const float*)d_in[15];
    const float* aW3 = (const float*)d_in[16];
    const float* ab3 = (const float*)d_in[17];
    const float* logstd = (const float*)d_in[18];
    const float* L      = (const float*)d_in[19];
    const float* s0     = (const float*)d_in[20];

    const int N = in_sizes[0] / OBS;
    float* out = (float*)d_out;

    // Large shared carveout: 3 x 57.2KB blocks need ~172KB.
    cudaFuncSetAttribute(fused_kernel,
                         cudaFuncAttributePreferredSharedMemoryCarveout, 100);

    const int rowsPerBlock = 2 * TPB;
    const int halfBlocks = (N + rowsPerBlock - 1) / rowsPerBlock;
    fused_kernel<<<2 * halfBlocks, TPB>>>(x, sdfs, grads, f_x, g_x, action,
                                          cW1, cb1, cW2, cb2, cW3, cb3,
                                          aW1, ab1, aW2, ab2, aW3, ab3,
                                          logstd, L, s0, out, N, halfBlocks);
}

// round 16
// speedup vs baseline: 1.3101x; 1.1423x over previous
#include <cuda_runtime.h>
#include <cuda_fp16.h>
#include <math.h>

#define OBS 17
#define ACT 4
#define HID 64
#define LOG_2PI 1.8378770664093453f
#define TPB 128
typedef unsigned long long ull;

// ---- shared buffer layout (float offsets) ----
#define F_W1   0       // 17*64 = 1088
#define F_W2   1088    // 64*64 = 4096
#define F_W3   5184    // actor: 256 ; critic: 64
#define F_B1   5440    // 64
#define F_B2   5504    // 64
#define F_B3   5568    // 4
#define F_LOG  5572    // 4
#define F_INV  5576    // 4
#define F_QINV 5584    // 16
#define F_MISC 5600    // 0: s0|cb3, 1: entropy
#define F_XT   5604    // 128*17 = 2176 : x tile for ONE 128-row pass
#define SM_FLOATS 7780

__device__ __forceinline__ float tanh_fast(float v) {
    float r; asm("tanh.approx.f32 %0, %1;" : "=f"(r) : "f"(v)); return r;
}
__device__ __forceinline__ ull fma2(ull a, ull b, ull c) {
    ull d; asm("fma.rn.f32x2 %0, %1, %2, %3;" : "=l"(d) : "l"(a), "l"(b), "l"(c)); return d;
}
__device__ __forceinline__ ull dup2(float v) {
    ull d; asm("mov.b64 %0, {%1, %1};" : "=l"(d) : "f"(v)); return d;
}
__device__ __forceinline__ ull pk2(float x, float y) {
    ull d; asm("mov.b64 %0, {%1, %2};" : "=l"(d) : "f"(x), "f"(y)); return d;
}
__device__ __forceinline__ float2 upk(ull p) {
    float2 r; asm("mov.b64 {%0, %1}, %2;" : "=f"(r.x), "=f"(r.y) : "l"(p)); return r;
}

// fp32 4x4 SPD inverse: Gauss-Jordan w/ pivoting + 2 Newton refinements.
__device__ void qinv_f32(const float* __restrict__ L, float* __restrict__ outQinv) {
    float Q[16], M[4][8];
#pragma unroll
    for (int i = 0; i < 4; i++)
#pragma unroll
        for (int j = 0; j < 4; j++) {
            float s = (i == j) ? 1e-4f : 0.0f;
#pragma unroll
            for (int k = 0; k < 4; k++)
                if (k <= i && k <= j) s += L[i * 4 + k] * L[j * 4 + k];
            Q[i * 4 + j] = s;
        }
#pragma unroll
    for (int i = 0; i < 4; i++)
#pragma unroll
        for (int j = 0; j < 4; j++) {
            M[i][j] = Q[i * 4 + j];
            M[i][4 + j] = (i == j) ? 1.0f : 0.0f;
        }
    for (int c = 0; c < 4; c++) {
        int p = c;
        for (int r = c + 1; r < 4; r++) if (fabsf(M[r][c]) > fabsf(M[p][c])) p = r;
        if (p != c)
            for (int j = 0; j < 8; j++) { float t = M[c][j]; M[c][j] = M[p][j]; M[p][j] = t; }
        const float inv = 1.0f / M[c][c];
        for (int j = 0; j < 8; j++) M[c][j] *= inv;
        for (int r = 0; r < 4; r++) if (r != c) {
            const float f = M[r][c];
            for (int j = 0; j < 8; j++) M[r][j] -= f * M[c][j];
        }
    }
    float X[16];
#pragma unroll
    for (int i = 0; i < 4; i++)
#pragma unroll
        for (int j = 0; j < 4; j++) X[i * 4 + j] = M[i][4 + j];
#pragma unroll 1
    for (int it = 0; it < 2; it++) {
        float R[16];
#pragma unroll
        for (int i = 0; i < 4; i++)
#pragma unroll
            for (int j = 0; j < 4; j++) {
                float s = (i == j) ? 2.0f : 0.0f;
#pragma unroll
                for (int k = 0; k < 4; k++) s -= Q[i * 4 + k] * X[k * 4 + j];
                R[i * 4 + j] = s;
            }
        float Xn[16];
#pragma unroll
        for (int i = 0; i < 4; i++)
#pragma unroll
            for (int j = 0; j < 4; j++) {
                float s = 0.0f;
#pragma unroll
                for (int k = 0; k < 4; k++) s += X[i * 4 + k] * R[k * 4 + j];
                Xn[i * 4 + j] = s;
            }
#pragma unroll
        for (int i = 0; i < 16; i++) X[i] = Xn[i];
    }
#pragma unroll
    for (int i = 0; i < 16; i++) outQinv[i] = X[i];
}

// ---------------------------------------------------------------------------
// Fat-grid kernel; x staged in two 128-row passes to cut register pressure.
// blocks [0, half) = actor, [half, 2*half) = critic; 2 rows/thread.
// ---------------------------------------------------------------------------
__global__ __launch_bounds__(TPB, 4) void fused_kernel(
    const float* __restrict__ x, const float* __restrict__ sdfs,
    const float* __restrict__ grads, const float* __restrict__ f_x,
    const float* __restrict__ g_x, const float* __restrict__ action,
    const float* __restrict__ cW1, const float* __restrict__ cb1,
    const float* __restrict__ cW2, const float* __restrict__ cb2,
    const float* __restrict__ cW3, const float* __restrict__ cb3,
    const float* __restrict__ aW1, const float* __restrict__ ab1,
    const float* __restrict__ aW2, const float* __restrict__ ab2,
    const float* __restrict__ aW3, const float* __restrict__ ab3,
    const float* __restrict__ logstd, const float* __restrict__ L,
    const float* __restrict__ s0,
    float* __restrict__ out, int N, int halfBlocks)
{
    __shared__ __align__(16) float sm[SM_FLOATS];
    const int tid = threadIdx.x;
    const bool isActor = (int)blockIdx.x < halfBlocks;
    const int blk = isActor ? (int)blockIdx.x : (int)blockIdx.x - halfBlocks;
    const int blockStart = blk * (2 * TPB);

    // ================= staging (weights etc.) =================
    if (isActor) {
        for (int i = tid; i < OBS * HID; i += TPB) sm[F_W1 + i] = aW1[i];
        for (int i = tid; i < HID * HID; i += TPB) sm[F_W2 + i] = aW2[i];
        for (int i = tid; i < HID * ACT; i += TPB) sm[F_W3 + i] = aW3[i];
        if (tid < HID) { sm[F_B1 + tid] = ab1[tid]; sm[F_B2 + tid] = ab2[tid]; }
        if (tid >= 64 && tid < 68) {
            const int a = tid - 64;
            const float ls = logstd[a];
            sm[F_B3 + a] = ab3[a]; sm[F_LOG + a] = ls; sm[F_INV + a] = expf(-ls);
        }
        if (tid == 1) {
            sm[F_MISC + 0] = s0[0];
            float e = 0.0f;
            for (int a = 0; a < ACT; a++) e += 0.5f + 0.5f * LOG_2PI + logstd[a];
            sm[F_MISC + 1] = e;
        }
        if (tid == 0) qinv_f32(L, &sm[F_QINV]);
    } else {
        for (int i = tid; i < OBS * HID; i += TPB) sm[F_W1 + i] = cW1[i];
        for (int i = tid; i < HID * HID; i += TPB) sm[F_W2 + i] = cW2[i];
        if (tid < HID) {
            sm[F_W3 + tid] = cW3[tid];
            sm[F_B1 + tid] = cb1[tid];
            sm[F_B2 + tid] = cb2[tid];
        }
        if (tid == 0) sm[F_MISC + 0] = cb3[0];
    }

    const int r0 = blockStart + tid;
    const int r1 = r0 + TPB;
    const bool ok0 = r0 < N, ok1 = r1 < N;

    __half2 h1A[32], h1B[32];

    // ================= layer 1, two passes (x tile reused) =================
#pragma unroll 1
    for (int pass = 0; pass < 2; pass++) {
        // stage this pass's 128-row x tile (coalesced)
        const int passStart = blockStart + pass * TPB;
        if (passStart + TPB <= N) {
            const float4* gx4 = (const float4*)(x + passStart * OBS);
            float4* sx4 = (float4*)&sm[F_XT];
            for (int i = tid; i < TPB * OBS / 4; i += TPB) sx4[i] = gx4[i];
        } else {
            const int lim = N * OBS;
            for (int i = tid; i < TPB * OBS; i += TPB) {
                const int g = passStart * OBS + i;
                sm[F_XT + i] = (g < lim) ? x[g] : 0.0f;
            }
        }
        __syncthreads();

        __half2* h1 = pass ? h1B : h1A;
#pragma unroll 1
        for (int c1 = 0; c1 < 2; c1++) {
            ull h[16];
            const ulonglong2* bp = (const ulonglong2*)&sm[F_B1 + c1 * 32];
#pragma unroll
            for (int q = 0; q < 8; q++) {
                ulonglong2 bb = bp[q];
                h[2*q] = bb.x; h[2*q+1] = bb.y;
            }
#pragma unroll 1
            for (int i = 0; i < OBS; i++) {
                const ull v = dup2(sm[F_XT + tid * OBS + i]);
                const ulonglong2* wp = (const ulonglong2*)&sm[F_W1 + i * HID + c1 * 32];
#pragma unroll
                for (int q = 0; q < 8; q++) {
                    ulonglong2 ww = wp[q];
                    h[2*q]   = fma2(ww.x, v, h[2*q]);
                    h[2*q+1] = fma2(ww.y, v, h[2*q+1]);
                }
            }
#pragma unroll
            for (int p = 0; p < 16; p++) {
                float2 t = upk(h[p]);
                h1[c1 * 16 + p] = __floats2half2_rn(tanh_fast(t.x), tanh_fast(t.y));
            }
        }
        __syncthreads();   // all readers done before next pass overwrites tile
    }

    // ================= layer 2 + fused layer 3 =================
    ull mA01, mA23, mB01, mB23;   // actor: mean pairs ; critic: value in mA01/mB01
    if (isActor) {
        mA01 = pk2(sm[F_B3 + 0], sm[F_B3 + 1]);
        mA23 = pk2(sm[F_B3 + 2], sm[F_B3 + 3]);
        mB01 = mA01; mB23 = mA23;
    } else {
        mA01 = pk2(sm[F_MISC + 0], 0.0f);
        mB01 = mA01; mA23 = 0ull; mB23 = 0ull;
    }
#pragma unroll 1
    for (int c = 0; c < 4; c++) {
        ull aA[8], aB[8];
        const ulonglong2* bp = (const ulonglong2*)&sm[F_B2 + c * 16];
#pragma unroll
        for (int q = 0; q < 4; q++) {
            ulonglong2 bb = bp[q];
            aA[2*q] = bb.x; aA[2*q+1] = bb.y;
            aB[2*q] = bb.x; aB[2*q+1] = bb.y;
        }
#pragma unroll 4
        for (int ii = 0; ii < 32; ii++) {
            const float2 fA = __half22float2(h1A[ii]);
            const float2 fB = __half22float2(h1B[ii]);
            const ull a0 = dup2(fA.x), a1 = dup2(fA.y);
            const ull b0 = dup2(fB.x), b1 = dup2(fB.y);
            const ulonglong2* wp0 = (const ulonglong2*)&sm[F_W2 + (2*ii) * HID + c * 16];
            const ulonglong2* wp1 = (const ulonglong2*)&sm[F_W2 + (2*ii + 1) * HID + c * 16];
#pragma unroll
            for (int q = 0; q < 4; q++) {
                ulonglong2 w0 = wp0[q];
                aA[2*q]   = fma2(w0.x, a0, aA[2*q]);
                aA[2*q+1] = fma2(w0.y, a0, aA[2*q+1]);
                aB[2*q]   = fma2(w0.x, b0, aB[2*q]);
                aB[2*q+1] = fma2(w0.y, b0, aB[2*q+1]);
            }
#pragma unroll
            for (int q = 0; q < 4; q++) {
                ulonglong2 w1 = wp1[q];
                aA[2*q]   = fma2(w1.x, a1, aA[2*q]);
                aA[2*q+1] = fma2(w1.y, a1, aA[2*q+1]);
                aB[2*q]   = fma2(w1.x, b1, aB[2*q]);
                aB[2*q+1] = fma2(w1.y, b1, aB[2*q+1]);
            }
        }
#pragma unroll
        for (int p = 0; p < 8; p++) {
            const int j = c * 16 + 2 * p;
            float2 tA = upk(aA[p]);
            tA.x = tanh_fast(tA.x); tA.y = tanh_fast(tA.y);
            float2 tB = upk(aB[p]);
            tB.x = tanh_fast(tB.x); tB.y = tanh_fast(tB.y);
            if (isActor) {
                const ulonglong2 w0 = *(const ulonglong2*)&sm[F_W3 + j * ACT];
                const ulonglong2 w1 = *(const ulonglong2*)&sm[F_W3 + (j + 1) * ACT];
                ull d;
                d = dup2(tA.x); mA01 = fma2(w0.x, d, mA01); mA23 = fma2(w0.y, d, mA23);
                d = dup2(tA.y); mA01 = fma2(w1.x, d, mA01); mA23 = fma2(w1.y, d, mA23);
                d = dup2(tB.x); mB01 = fma2(w0.x, d, mB01); mB23 = fma2(w0.y, d, mB23);
                d = dup2(tB.y); mB01 = fma2(w1.x, d, mB01); mB23 = fma2(w1.y, d, mB23);
            } else {
                const ull wv = *(const ull*)&sm[F_W3 + j];
                mA01 = fma2(wv, pk2(tA.x, tA.y), mA01);
                mB01 = fma2(wv, pk2(tB.x, tB.y), mB01);
            }
        }
    }

    // ================= outputs =================
    if (!isActor) {
        const float2 a = upk(mA01);
        const float2 b = upk(mB01);
        if (ok0) out[6 * N + r0] = a.x + a.y;
        if (ok1) out[6 * N + r1] = b.x + b.y;
        return;
    }

#pragma unroll 1
    for (int rr = 0; rr < 2; rr++) {
        const int row = rr ? r1 : r0;
        const bool ok = rr ? ok1 : ok0;
        const int rl = ok ? row : 0;
        float m0, m1, m2, m3;
        {
            const float2 a = upk(rr ? mB01 : mA01);
            const float2 b = upk(rr ? mB23 : mA23);
            m0 = a.x; m1 = a.y; m2 = b.x; m3 = b.y;
        }
        float G0 = 0.f, G1 = 0.f, G2 = 0.f, G3 = 0.f, gf = 0.f;
#pragma unroll
        for (int s = 0; s < OBS; s++) {
            const float gr = grads[rl * OBS + s];
            const float4 gx = *(const float4*)&g_x[rl * OBS * ACT + s * ACT];
            G0 -= gr * gx.x; G1 -= gr * gx.y; G2 -= gr * gx.z; G3 -= gr * gx.w;
            gf += gr * f_x[rl * OBS + s];
        }
        const float4 av = *(const float4*)&action[rl * ACT];
        const float h = sm[F_MISC + 0] + sdfs[rl] + gf
                      - (G0 * av.x + G1 * av.y + G2 * av.z + G3 * av.w);
        const float* q = &sm[F_QINV];
        const float v0 = q[0]  * G0 + q[1]  * G1 + q[2]  * G2 + q[3]  * G3;
        const float v1 = q[4]  * G0 + q[5]  * G1 + q[6]  * G2 + q[7]  * G3;
        const float v2 = q[8]  * G0 + q[9]  * G1 + q[10] * G2 + q[11] * G3;
        const float v3 = q[12] * G0 + q[13] * G1 + q[14] * G2 + q[15] * G3;
        const float denom = G0 * v0 + G1 * v1 + G2 * v2 + G3 * v3;
        const float lam = fmaxf(0.0f, -h / denom);
        const float z0 = (av.x - m0) * sm[F_INV + 0];
        const float z1 = (av.y - m1) * sm[F_INV + 1];
        const float z2 = (av.z - m2) * sm[F_INV + 2];
        const float z3 = (av.w - m3) * sm[F_INV + 3];
        const float lp = -0.5f * (z0*z0 + z1*z1 + z2*z2 + z3*z3)
                       - (sm[F_LOG + 0] + sm[F_LOG + 1] + sm[F_LOG + 2] + sm[F_LOG + 3])
                       - 2.0f * LOG_2PI;
        if (ok) {
            *(float4*)&out[row * 4] = make_float4(m0 - lam * v0, m1 - lam * v1,
                                                  m2 - lam * v2, m3 - lam * v3);
            out[4 * N + row] = lp;
            out[5 * N + row] = sm[F_MISC + 1];
        }
    }
}

extern "C" void kernel_launch(void* const* d_in, const int* in_sizes, int n_in,
                              void* d_out, int out_size) {
    const float* x      = (const float*)d_in[0];
    const float* sdfs   = (const float*)d_in[1];
    const float* grads  = (const float*)d_in[2];
    const float* f_x    = (const float*)d_in[3];
    const float* g_x    = (const float*)d_in[4];
    const float* action = (const float*)d_in[5];
    const float* cW1 = (const float*)d_in[6];
    const float* cb1 = (const float*)d_in[7];
    const float* cW2 = (const float*)d_in[8];
    const float* cb2 = (const float*)d_in[9];
    const float* cW3 = (const float*)d_in[10];
    const float* cb3 = (const float*)d_in[11];
    const float* aW1 = (const float*)d_in[12];
    const float* ab1 = (const float*)d_in[13];
    const float* aW2 = (const float*)d_in[14];
    const float* ab2 = (const float*)d_in[15];
    const float* aW3 = (const float*)d_in[16];
    const float* ab3 = (const float*)d_in[17];
    const float* logstd = (const float*)d_in[18];
    const float* L      = (const float*)d_in[19];
    const float* s0     = (const float*)d_in[20];

    const int N = in_sizes[0] / OBS;
    float* out = (float*)d_out;

    // ~58% of 228KB -> 132KB shared tier: room for 4 x 31.1KB blocks
    // while keeping ~96KB L1 for the strided epilogue loads.
    cudaFuncSetAttribute(fused_kernel,
                         cudaFuncAttributePreferredSharedMemoryCarveout, 58);

    const int rowsPerBlock = 2 * TPB;
    const int halfBlocks = (N + rowsPerBlock - 1) / rowsPerBlock;
    fused_kernel<<<2 * halfBlocks, TPB>>>(x, sdfs, grads, f_x, g_x, action,
                                          cW1, cb1, cW2, cb2, cW3, cb3,
                                          aW1, ab1, aW2, ab2, aW3, ab3,
                                          logstd, L, s0, out, N, halfBlocks);
}